// round 2
// baseline (speedup 1.0000x reference)
#include <cuda_runtime.h>

#define BB 8
#define HH 512
#define WW 512
#define K2 9
#define HW (HH * WW)

__device__ __forceinline__ float samp(const float* __restrict__ img, int yi, int xi) {
    if (yi >= 0 && yi < HH && xi >= 0 && xi < WW)
        return __ldg(img + yi * WW + xi);
    return 0.0f;
}

__global__ __launch_bounds__(256) void deconv_post_kernel(
    const float* __restrict__ depth,
    const float* __restrict__ weight,
    const float* __restrict__ offset,
    float* __restrict__ out)
{
    int idx = blockIdx.x * blockDim.x + threadIdx.x;
    if (idx >= BB * HW) return;

    int x = idx % WW;
    int y = (idx / WW) % HH;
    int b = idx / HW;
    int pix = y * WW + x;

    const float* __restrict__ dimg = depth + b * HW;
    const float* __restrict__ wbase = weight + (long)b * K2 * HW + pix;
    const float* __restrict__ obase = offset + (long)b * 2 * K2 * HW + pix;

    // Stream all 27 per-pixel values up front (maximize MLP, coalesced in x)
    float wv[K2];
    float dyv[K2], dxv[K2];
#pragma unroll
    for (int k = 0; k < K2; k++) {
        wv[k] = __ldg(wbase + k * HW);
    }
#pragma unroll
    for (int k = 0; k < K2; k++) {
        dyv[k] = __ldg(obase + (2 * k) * HW);
        dxv[k] = __ldg(obase + (2 * k + 1) * HW);
    }

    float wsum = 0.0f;
#pragma unroll
    for (int k = 0; k < K2; k++) wsum += wv[k];
    float mean = wsum * (1.0f / 9.0f);

    float acc = 0.0f;
#pragma unroll
    for (int k = 0; k < K2; k++) {
        int ky = k / 3;
        int kx = k % 3;
        float py = dyv[k] + (float)(y - 1 + ky);
        float px = dxv[k] + (float)(x - 1 + kx);

        float y0f = floorf(py);
        float x0f = floorf(px);
        float ty = py - y0f;
        float tx = px - x0f;
        int y0 = (int)y0f;
        int x0 = (int)x0f;

        float v00 = samp(dimg, y0,     x0);
        float v01 = samp(dimg, y0,     x0 + 1);
        float v10 = samp(dimg, y0 + 1, x0);
        float v11 = samp(dimg, y0 + 1, x0 + 1);

        float v = v00 * (1.0f - ty) * (1.0f - tx)
                + v01 * (1.0f - ty) * tx
                + v10 * ty * (1.0f - tx)
                + v11 * ty * tx;

        acc += v * (wv[k] - mean);
    }

    out[idx] = acc + __ldg(dimg + pix);
}

extern "C" void kernel_launch(void* const* d_in, const int* in_sizes, int n_in,
                              void* d_out, int out_size) {
    const float* depth  = (const float*)d_in[0];
    const float* weight = (const float*)d_in[1];
    const float* offset = (const float*)d_in[2];
    float* out = (float*)d_out;

    int total = BB * HW;
    int threads = 256;
    int blocks = (total + threads - 1) / threads;
    deconv_post_kernel<<<blocks, threads>>>(depth, weight, offset, out);
}